// round 14
// baseline (speedup 1.0000x reference)
#include <cuda_runtime.h>
#include <cuda_bf16.h>
#include <cstdint>

#define BATCH 16
#define DIMC  256
#define NHEAD 8
#define CRCH  64
#define HH    64
#define WW    64
#define NPIX  (HH*WW)
#define QKVC  192
#define SCALE 0.17677669529663687f

__device__ __forceinline__ uint32_t smem_u32(const void* p) {
    uint32_t a;
    asm("{ .reg .u64 t; cvta.to.shared.u64 t, %1; cvt.u32.u64 %0, t; }" : "=r"(a) : "l"(p));
    return a;
}
__device__ __forceinline__ void ldsm4(uint32_t* r, uint32_t addr) {
    asm volatile("ldmatrix.sync.aligned.m8n8.x4.shared.b16 {%0,%1,%2,%3}, [%4];"
        : "=r"(r[0]), "=r"(r[1]), "=r"(r[2]), "=r"(r[3]) : "r"(addr));
}
__device__ __forceinline__ void mma16816(float* d, const uint32_t* a, const uint32_t* b) {
    asm volatile("mma.sync.aligned.m16n8k16.row.col.f32.bf16.bf16.f32 "
        "{%0,%1,%2,%3}, {%4,%5,%6,%7}, {%8,%9}, {%0,%1,%2,%3};"
        : "+f"(d[0]), "+f"(d[1]), "+f"(d[2]), "+f"(d[3])
        : "r"(a[0]), "r"(a[1]), "r"(a[2]), "r"(a[3]), "r"(b[0]), "r"(b[1]));
}
__device__ __forceinline__ void cpasync16(uint32_t dst, const void* src) {
    asm volatile("cp.async.cg.shared.global [%0], [%1], 16;" :: "r"(dst), "l"(src));
}
#define CP_COMMIT() asm volatile("cp.async.commit_group;" ::: "memory")

// ---------------- scratch ----------------
__device__ float g_qkv[(long)BATCH * QKVC * NPIX];            // (B,192,4096) fp32
__device__ __nv_bfloat16 g_xt_hi[(long)BATCH * NPIX * DIMC];  // (B,4096,256)
__device__ __nv_bfloat16 g_xt_lo[(long)BATCH * NPIX * DIMC];
__device__ __nv_bfloat16 g_at_hi[(long)BATCH * NPIX * CRCH];  // (B,4096,64)
__device__ __nv_bfloat16 g_at_lo[(long)BATCH * NPIX * CRCH];
__device__ __nv_bfloat16 g_w_hi[QKVC * DIMC];
__device__ __nv_bfloat16 g_w_lo[QKVC * DIMC];
__device__ __nv_bfloat16 g_pw_hi[DIMC * CRCH];
__device__ __nv_bfloat16 g_pw_lo[DIMC * CRCH];

// ---------------- weight split convert ----------------
__global__ void convert_split(const float* __restrict__ src,
                              __nv_bfloat16* __restrict__ hi,
                              __nv_bfloat16* __restrict__ lo, int n)
{
    int i = blockIdx.x * 256 + threadIdx.x;
    if (i < n) {
        float v = src[i];
        __nv_bfloat16 h = __float2bfloat16(v);
        hi[i] = h;
        lo[i] = __float2bfloat16(v - __bfloat162float(h));
    }
}

// ---------------- transpose + split convert of x ----------------
__global__ __launch_bounds__(256)
void tconv_x(const float* __restrict__ X,
             __nv_bfloat16* __restrict__ hi, __nv_bfloat16* __restrict__ lo)
{
    __shared__ float s[64][68];
    int b = blockIdx.z, c0 = blockIdx.y * 64, p0 = blockIdx.x * 64;
    const float* src = X + ((long)b * DIMC + c0) * NPIX + p0;
    int t = threadIdx.x;
    int lc = t >> 4, lp4 = (t & 15) * 4;
    #pragma unroll
    for (int i = 0; i < 4; i++) {
        float4 v = *(const float4*)(src + (long)(lc + i * 16) * NPIX + lp4);
        s[lc + i * 16][lp4 + 0] = v.x;
        s[lc + i * 16][lp4 + 1] = v.y;
        s[lc + i * 16][lp4 + 2] = v.z;
        s[lc + i * 16][lp4 + 3] = v.w;
    }
    __syncthreads();
    int lp = t >> 2, ch16 = (t & 3) * 16;
    unsigned hw[8], lw[8];
    #pragma unroll
    for (int j = 0; j < 8; j++) {
        float v0 = s[ch16 + 2 * j][lp];
        float v1 = s[ch16 + 2 * j + 1][lp];
        __nv_bfloat16 h0 = __float2bfloat16(v0);
        __nv_bfloat16 h1 = __float2bfloat16(v1);
        __nv_bfloat16 l0 = __float2bfloat16(v0 - __bfloat162float(h0));
        __nv_bfloat16 l1 = __float2bfloat16(v1 - __bfloat162float(h1));
        hw[j] = (unsigned)__bfloat16_as_ushort(h0) | ((unsigned)__bfloat16_as_ushort(h1) << 16);
        lw[j] = (unsigned)__bfloat16_as_ushort(l0) | ((unsigned)__bfloat16_as_ushort(l1) << 16);
    }
    long ob = ((long)b * NPIX + p0 + lp) * DIMC + c0 + ch16;
    *(uint4*)(hi + ob)     = make_uint4(hw[0], hw[1], hw[2], hw[3]);
    *(uint4*)(hi + ob + 8) = make_uint4(hw[4], hw[5], hw[6], hw[7]);
    *(uint4*)(lo + ob)     = make_uint4(lw[0], lw[1], lw[2], lw[3]);
    *(uint4*)(lo + ob + 8) = make_uint4(lw[4], lw[5], lw[6], lw[7]);
}

// ---------------- HMMA bf16x3 GEMM, multi-stage cp.async ring ----------------
// C[b][ch][pix] = sum_k W[ch][k] * Xt[b][pix][k]  (+bias), fp32 accum.
// 3 split passes: Wh*Xh + Wh*Xl + Wl*Xh.
// KC-wide k-chunks, STAGES smem buffers; one commit group per iteration
// (empty on tail) so wait_group STAGES-1 always guarantees chunk ck resident.
template <int NCHT, int KD, int KC, int STAGES, int MW, int NW, int MF, int NF>
__global__ __launch_bounds__(256)
void gemm_mma(const __nv_bfloat16* __restrict__ Whi, const __nv_bfloat16* __restrict__ Wlo,
              const __nv_bfloat16* __restrict__ Xhi, const __nv_bfloat16* __restrict__ Xlo,
              const float* __restrict__ bias, float* __restrict__ C)
{
    constexpr int MT = MW * MF * 16;        // channel tile
    constexpr int CHUNKS = KD / KC;
    constexpr int ROWB = KC * 2 + 16;       // bytes per smem row (odd x16B)
    constexpr int QPR = KC / 8;             // uint4 per row
    constexpr int BUF = (2 * MT + 2 * 128) * ROWB;
    const int OF_AH = 0;
    const int OF_AL = MT * ROWB;
    const int OF_BH = 2 * MT * ROWB;
    const int OF_BL = 2 * MT * ROWB + 128 * ROWB;

    extern __shared__ char sm[];
    int tid = threadIdx.x;
    int wid = tid >> 5, lane = tid & 31;
    int pix0 = blockIdx.x * 128;
    int bb = blockIdx.y;
    int m0 = blockIdx.z * MT;

    uint32_t sbase = smem_u32(sm);

    int wm = wid % MW, wn = wid / MW;
    int mwo = wm * MF * 16;
    int nwo = wn * NF * 8;

    const __nv_bfloat16* Xh = Xhi + (long)bb * NPIX * KD;
    const __nv_bfloat16* Xl = Xlo + (long)bb * NPIX * KD;

    float acc[MF][NF][4];
    #pragma unroll
    for (int i = 0; i < MF; i++)
        #pragma unroll
        for (int j = 0; j < NF; j++)
            #pragma unroll
            for (int q = 0; q < 4; q++) acc[i][j][q] = 0.f;

    int a_row = lane & 15, a_col = (lane >> 4) << 3;
    int b_nrow = ((lane >> 4) << 3) + (lane & 7);
    int b_kcol = ((lane >> 3) & 1) << 3;

    auto prefetch = [&](int ck, int bsel) {
        uint32_t bpa = sbase + bsel * BUF;
        for (int i = tid; i < MT * QPR; i += 256) {
            int row = i / QPR, q = i % QPR;
            long src = (long)(m0 + row) * KD + ck * KC + q * 8;
            cpasync16(bpa + OF_AH + row * ROWB + q * 16, Whi + src);
            cpasync16(bpa + OF_AL + row * ROWB + q * 16, Wlo + src);
        }
        for (int i = tid; i < 128 * QPR; i += 256) {
            int row = i / QPR, q = i % QPR;
            long src = (long)(pix0 + row) * KD + ck * KC + q * 8;
            cpasync16(bpa + OF_BH + row * ROWB + q * 16, Xh + src);
            cpasync16(bpa + OF_BL + row * ROWB + q * 16, Xl + src);
        }
    };

    // prologue: stages 0..STAGES-2
    for (int s = 0; s < STAGES - 1; s++) {
        if (s < CHUNKS) prefetch(s, s);
        CP_COMMIT();
    }

    for (int ck = 0; ck < CHUNKS; ck++) {
        int pf = ck + STAGES - 1;
        if (pf < CHUNKS) prefetch(pf, pf % STAGES);
        CP_COMMIT();
        asm volatile("cp.async.wait_group %0;" :: "n"(STAGES - 1) : "memory");
        __syncthreads();

        uint32_t bpa = sbase + (ck % STAGES) * BUF;
        #pragma unroll
        for (int ks = 0; ks < KC / 16; ks++) {
            int ko = ks * 16;
            uint32_t ah[MF][4], al[MF][4], bh[NF][2], bl[NF][2];
            #pragma unroll
            for (int mi = 0; mi < MF; mi++) {
                uint32_t off = (mwo + mi * 16 + a_row) * ROWB + (ko + a_col) * 2;
                ldsm4(ah[mi], bpa + OF_AH + off);
                ldsm4(al[mi], bpa + OF_AL + off);
            }
            #pragma unroll
            for (int nj2 = 0; nj2 < NF / 2; nj2++) {
                uint32_t off = (nwo + nj2 * 16 + b_nrow) * ROWB + (ko + b_kcol) * 2;
                uint32_t t4[4];
                ldsm4(t4, bpa + OF_BH + off);
                bh[2 * nj2][0] = t4[0]; bh[2 * nj2][1] = t4[1];
                bh[2 * nj2 + 1][0] = t4[2]; bh[2 * nj2 + 1][1] = t4[3];
                ldsm4(t4, bpa + OF_BL + off);
                bl[2 * nj2][0] = t4[0]; bl[2 * nj2][1] = t4[1];
                bl[2 * nj2 + 1][0] = t4[2]; bl[2 * nj2 + 1][1] = t4[3];
            }
            #pragma unroll
            for (int mi = 0; mi < MF; mi++)
                #pragma unroll
                for (int nj = 0; nj < NF; nj++) {
                    mma16816(acc[mi][nj], ah[mi], bh[nj]);
                    mma16816(acc[mi][nj], ah[mi], bl[nj]);
                    mma16816(acc[mi][nj], al[mi], bh[nj]);
                }
        }
        __syncthreads();   // all warps done with this buffer before it is reused
    }

    // epilogue: bias + float2 stores into [b][ch][pix]
    int chl = lane >> 2, pxl = (lane & 3) << 1;
    #pragma unroll
    for (int mi = 0; mi < MF; mi++) {
        int ch = m0 + mwo + mi * 16 + chl;
        float bi0 = bias[ch], bi1 = bias[ch + 8];
        float* Crow0 = C + ((long)bb * NCHT + ch) * NPIX + pix0;
        float* Crow1 = Crow0 + 8 * NPIX;
        #pragma unroll
        for (int nj = 0; nj < NF; nj++) {
            int px = nwo + nj * 8 + pxl;
            *(float2*)(Crow0 + px) = make_float2(acc[mi][nj][0] + bi0, acc[mi][nj][1] + bi0);
            *(float2*)(Crow1 + px) = make_float2(acc[mi][nj][2] + bi1, acc[mi][nj][3] + bi1);
        }
    }
}

// ---------------- slide attention (scalar core, bf16 hi/lo epilogue) ----------------
__device__ __forceinline__ void store8_split(__nv_bfloat16* hi, __nv_bfloat16* lo,
                                             long off, const float* v)
{
    unsigned hw[4], lw[4];
    #pragma unroll
    for (int j = 0; j < 4; j++) {
        __nv_bfloat16 h0 = __float2bfloat16(v[2 * j]);
        __nv_bfloat16 h1 = __float2bfloat16(v[2 * j + 1]);
        __nv_bfloat16 l0 = __float2bfloat16(v[2 * j] - __bfloat162float(h0));
        __nv_bfloat16 l1 = __float2bfloat16(v[2 * j + 1] - __bfloat162float(h1));
        hw[j] = (unsigned)__bfloat16_as_ushort(h0) | ((unsigned)__bfloat16_as_ushort(h1) << 16);
        lw[j] = (unsigned)__bfloat16_as_ushort(l0) | ((unsigned)__bfloat16_as_ushort(l1) << 16);
    }
    *(uint4*)(hi + off) = make_uint4(hw[0], hw[1], hw[2], hw[3]);
    *(uint4*)(lo + off) = make_uint4(lw[0], lw[1], lw[2], lw[3]);
}

__global__ __launch_bounds__(256)
void attn_kernel(const float* __restrict__ qkv,
                 const float* __restrict__ dep_b0,
                 const float* __restrict__ dep_b1,
                 const float* __restrict__ W1,
                 const float* __restrict__ rpb,
                 __nv_bfloat16* __restrict__ at_hi,
                 __nv_bfloat16* __restrict__ at_lo)
{
    __shared__ float sk[8][18][34];
    __shared__ float sv[8][18][34];
    __shared__ float sw1[72][9];
    __shared__ float sb[72];
    __shared__ float srpb[9];

    int bz = blockIdx.z;
    int b = bz >> 3, nh = bz & 7;
    int x0 = blockIdx.x * 32, y0 = blockIdx.y * 16;
    int tid = threadIdx.x;
    int tx = tid & 15, ty = tid >> 4;

    const float* base = qkv + ((long)b * QKVC + 24 * nh) * NPIX;

    for (int i = tid; i < 8 * 18 * 34; i += 256) {
        int c = i / 612;
        int r = (i / 34) % 18;
        int col = i % 34;
        int gy = y0 + r - 1, gx = x0 + col - 1;
        float kv = 0.f, vv = 0.f;
        if ((unsigned)gy < 64u && (unsigned)gx < 64u) {
            long off = (long)(8 + c) * NPIX + gy * WW + gx;
            kv = base[off];
            vv = base[off + 8 * NPIX];
        }
        sk[c][r][col] = kv;
        sv[c][r][col] = vv;
    }
    if (tid < 72) sb[tid] = dep_b0[tid] + dep_b1[tid];
    for (int i = tid; i < 72 * 9; i += 256) sw1[i / 9][i % 9] = W1[i];
    if (tid < 9) srpb[tid] = rpb[nh * 9 + tid];
    __syncthreads();

    int pA = (y0 + ty) * WW + (x0 + tx);
    int pB = pA + 16;
    int ly = ty + 1, lxA = tx + 1, lxB = tx + 17;

    float logA[9], logB[9];
    #pragma unroll
    for (int t = 0; t < 9; t++) { logA[t] = 0.f; logB[t] = 0.f; }

    #pragma unroll
    for (int c = 0; c < 8; c++) {
        float qa = base[(long)c * NPIX + pA] * SCALE;
        float qb = base[(long)c * NPIX + pB] * SCALE;
        float nbA[9], nbB[9];
        #pragma unroll
        for (int t = 0; t < 9; t++) {
            int dy = t / 3 - 1, dx = t % 3 - 1;
            nbA[t] = sk[c][ly + dy][lxA + dx];
            nbB[t] = sk[c][ly + dy][lxB + dx];
        }
        #pragma unroll
        for (int t = 0; t < 9; t++) {
            float bias = sb[c * 9 + t] + srpb[t];
            float kA = nbA[t] + bias;
            float kB = nbB[t] + bias;
            #pragma unroll
            for (int s = 0; s < 9; s++) {
                float w = sw1[c * 9 + t][s];
                kA += w * nbA[s];
                kB += w * nbB[s];
            }
            logA[t] += qa * kA;
            logB[t] += qb * kB;
        }
    }

    float mA = logA[0], mB = logB[0];
    #pragma unroll
    for (int t = 1; t < 9; t++) { mA = fmaxf(mA, logA[t]); mB = fmaxf(mB, logB[t]); }
    float sumA = 0.f, sumB = 0.f;
    #pragma unroll
    for (int t = 0; t < 9; t++) {
        logA[t] = __expf(logA[t] - mA); sumA += logA[t];
        logB[t] = __expf(logB[t] - mB); sumB += logB[t];
    }
    float invA = 1.f / sumA, invB = 1.f / sumB;

    float outA[8], outB[8];
    #pragma unroll
    for (int c = 0; c < 8; c++) {
        float nbA[9], nbB[9];
        #pragma unroll
        for (int t = 0; t < 9; t++) {
            int dy = t / 3 - 1, dx = t % 3 - 1;
            nbA[t] = sv[c][ly + dy][lxA + dx];
            nbB[t] = sv[c][ly + dy][lxB + dx];
        }
        float oA = 0.f, oB = 0.f;
        #pragma unroll
        for (int t = 0; t < 9; t++) {
            float bias = sb[c * 9 + t];
            float vA = nbA[t] + bias;
            float vB = nbB[t] + bias;
            #pragma unroll
            for (int s = 0; s < 9; s++) {
                float w = sw1[c * 9 + t][s];
                vA += w * nbA[s];
                vB += w * nbB[s];
            }
            oA += logA[t] * vA;
            oB += logB[t] * vB;
        }
        outA[c] = oA * invA;
        outB[c] = oB * invB;
    }
    long rowA = ((long)b * NPIX + pA) * CRCH + nh * 8;
    long rowB = ((long)b * NPIX + pB) * CRCH + nh * 8;
    store8_split(at_hi, at_lo, rowA, outA);
    store8_split(at_hi, at_lo, rowB, outB);
}

// ---------------- launch ----------------
extern "C" void kernel_launch(void* const* d_in, const int* in_sizes, int n_in,
                              void* d_out, int out_size)
{
    const float* x      = (const float*)d_in[0];
    const float* qkv_w  = (const float*)d_in[5];
    const float* qkv_b  = (const float*)d_in[6];
    const float* dep_b0 = (const float*)d_in[7];
    const float* W1     = (const float*)d_in[8];
    const float* dep_b1 = (const float*)d_in[9];
    const float* rpb    = (const float*)d_in[10];
    const float* proj_w = (const float*)d_in[11];
    const float* proj_b = (const float*)d_in[12];
    float* out = (float*)d_out;

    float* qkvbuf; cudaGetSymbolAddress((void**)&qkvbuf, g_qkv);
    __nv_bfloat16 *xth, *xtl, *ath, *atl, *wh, *wl, *pwh, *pwl;
    cudaGetSymbolAddress((void**)&xth, g_xt_hi);
    cudaGetSymbolAddress((void**)&xtl, g_xt_lo);
    cudaGetSymbolAddress((void**)&ath, g_at_hi);
    cudaGetSymbolAddress((void**)&atl, g_at_lo);
    cudaGetSymbolAddress((void**)&wh, g_w_hi);
    cudaGetSymbolAddress((void**)&wl, g_w_lo);
    cudaGetSymbolAddress((void**)&pwh, g_pw_hi);
    cudaGetSymbolAddress((void**)&pwl, g_pw_lo);

    // GEMM1: MT=192, KC=32, CHUNKS=8, 4-stage ring
    // GEMM3: MT=128 (2 z-slices), KC=16, CHUNKS=4, 4-stage ring
    auto k1 = gemm_mma<QKVC, DIMC, 32, 4, 4, 2, 3, 8>;
    auto k3 = gemm_mma<DIMC, CRCH, 16, 4, 2, 4, 4, 4>;
    const int SMEM1 = 4 * (2 * 192 + 2 * 128) * 80;   // 204800
    const int SMEM3 = 4 * (2 * 128 + 2 * 128) * 48;   // 98304
    cudaFuncSetAttribute(k1, cudaFuncAttributeMaxDynamicSharedMemorySize, SMEM1);
    cudaFuncSetAttribute(k3, cudaFuncAttributeMaxDynamicSharedMemorySize, SMEM3);

    // weight splits
    convert_split<<<(QKVC * DIMC + 255) / 256, 256>>>(qkv_w, wh, wl, QKVC * DIMC);
    convert_split<<<(DIMC * CRCH + 255) / 256, 256>>>(proj_w, pwh, pwl, DIMC * CRCH);

    // x transpose+split
    tconv_x<<<dim3(NPIX / 64, DIMC / 64, BATCH), 256>>>(x, xth, xtl);

    // GEMM1 -> qkv fp32 [b][192][4096]
    k1<<<dim3(NPIX / 128, BATCH, 1), 256, SMEM1>>>(wh, wl, xth, xtl, qkv_b, qkvbuf);

    // attention -> at hi/lo [b][pix][64]
    attn_kernel<<<dim3(2, 4, BATCH * NHEAD), 256>>>(
        qkvbuf, dep_b0, dep_b1, W1, rpb, ath, atl);

    // GEMM3 -> out [b][256][4096]
    k3<<<dim3(NPIX / 128, BATCH, 2), 256, SMEM3>>>(pwh, pwl, ath, atl, proj_b, out);
}

// round 15
// speedup vs baseline: 1.1129x; 1.1129x over previous
#include <cuda_runtime.h>
#include <cuda_bf16.h>
#include <cstdint>

#define BATCH 16
#define DIMC  256
#define NHEAD 8
#define CRCH  64
#define HH    64
#define WW    64
#define NPIX  (HH*WW)
#define QKVC  192
#define SCALE 0.17677669529663687f

typedef unsigned long long u64;

__device__ __forceinline__ uint32_t smem_u32(const void* p) {
    uint32_t a;
    asm("{ .reg .u64 t; cvta.to.shared.u64 t, %1; cvt.u32.u64 %0, t; }" : "=r"(a) : "l"(p));
    return a;
}
__device__ __forceinline__ void ldsm4(uint32_t* r, uint32_t addr) {
    asm volatile("ldmatrix.sync.aligned.m8n8.x4.shared.b16 {%0,%1,%2,%3}, [%4];"
        : "=r"(r[0]), "=r"(r[1]), "=r"(r[2]), "=r"(r[3]) : "r"(addr));
}
__device__ __forceinline__ void mma16816(float* d, const uint32_t* a, const uint32_t* b) {
    asm volatile("mma.sync.aligned.m16n8k16.row.col.f32.bf16.bf16.f32 "
        "{%0,%1,%2,%3}, {%4,%5,%6,%7}, {%8,%9}, {%0,%1,%2,%3};"
        : "+f"(d[0]), "+f"(d[1]), "+f"(d[2]), "+f"(d[3])
        : "r"(a[0]), "r"(a[1]), "r"(a[2]), "r"(a[3]), "r"(b[0]), "r"(b[1]));
}
__device__ __forceinline__ void cpasync16(uint32_t dst, const void* src) {
    asm volatile("cp.async.cg.shared.global [%0], [%1], 16;" :: "r"(dst), "l"(src));
}
#define CP_COMMIT() asm volatile("cp.async.commit_group;" ::: "memory")

// f32x2 packed helpers
__device__ __forceinline__ u64 pk2(float lo, float hi) {
    u64 r; asm("mov.b64 %0, {%1, %2};" : "=l"(r) : "f"(lo), "f"(hi)); return r;
}
__device__ __forceinline__ void upk2(u64 v, float& lo, float& hi) {
    asm("mov.b64 {%0, %1}, %2;" : "=f"(lo), "=f"(hi) : "l"(v));
}
__device__ __forceinline__ u64 fma2(u64 a, u64 b, u64 c) {
    u64 r; asm("fma.rn.f32x2 %0, %1, %2, %3;" : "=l"(r) : "l"(a), "l"(b), "l"(c)); return r;
}
__device__ __forceinline__ u64 add2_(u64 a, u64 b) {
    u64 r; asm("add.rn.f32x2 %0, %1, %2;" : "=l"(r) : "l"(a), "l"(b)); return r;
}

// ---------------- scratch ----------------
__device__ float g_qkv[(long)BATCH * QKVC * NPIX];            // (B,192,4096) fp32
__device__ __nv_bfloat16 g_xt_hi[(long)BATCH * NPIX * DIMC];  // (B,4096,256)
__device__ __nv_bfloat16 g_xt_lo[(long)BATCH * NPIX * DIMC];
__device__ __nv_bfloat16 g_at_hi[(long)BATCH * NPIX * CRCH];  // (B,4096,64)
__device__ __nv_bfloat16 g_at_lo[(long)BATCH * NPIX * CRCH];
__device__ __nv_bfloat16 g_w_hi[QKVC * DIMC];
__device__ __nv_bfloat16 g_w_lo[QKVC * DIMC];
__device__ __nv_bfloat16 g_pw_hi[DIMC * CRCH];
__device__ __nv_bfloat16 g_pw_lo[DIMC * CRCH];

// ---------------- weight split convert ----------------
__global__ void convert_split(const float* __restrict__ src,
                              __nv_bfloat16* __restrict__ hi,
                              __nv_bfloat16* __restrict__ lo, int n)
{
    int i = blockIdx.x * 256 + threadIdx.x;
    if (i < n) {
        float v = src[i];
        __nv_bfloat16 h = __float2bfloat16(v);
        hi[i] = h;
        lo[i] = __float2bfloat16(v - __bfloat162float(h));
    }
}

// ---------------- transpose + split convert of x ----------------
__global__ __launch_bounds__(256)
void tconv_x(const float* __restrict__ X,
             __nv_bfloat16* __restrict__ hi, __nv_bfloat16* __restrict__ lo)
{
    __shared__ float s[64][68];
    int b = blockIdx.z, c0 = blockIdx.y * 64, p0 = blockIdx.x * 64;
    const float* src = X + ((long)b * DIMC + c0) * NPIX + p0;
    int t = threadIdx.x;
    int lc = t >> 4, lp4 = (t & 15) * 4;
    #pragma unroll
    for (int i = 0; i < 4; i++) {
        float4 v = *(const float4*)(src + (long)(lc + i * 16) * NPIX + lp4);
        s[lc + i * 16][lp4 + 0] = v.x;
        s[lc + i * 16][lp4 + 1] = v.y;
        s[lc + i * 16][lp4 + 2] = v.z;
        s[lc + i * 16][lp4 + 3] = v.w;
    }
    __syncthreads();
    int lp = t >> 2, ch16 = (t & 3) * 16;
    unsigned hw[8], lw[8];
    #pragma unroll
    for (int j = 0; j < 8; j++) {
        float v0 = s[ch16 + 2 * j][lp];
        float v1 = s[ch16 + 2 * j + 1][lp];
        __nv_bfloat16 h0 = __float2bfloat16(v0);
        __nv_bfloat16 h1 = __float2bfloat16(v1);
        __nv_bfloat16 l0 = __float2bfloat16(v0 - __bfloat162float(h0));
        __nv_bfloat16 l1 = __float2bfloat16(v1 - __bfloat162float(h1));
        hw[j] = (unsigned)__bfloat16_as_ushort(h0) | ((unsigned)__bfloat16_as_ushort(h1) << 16);
        lw[j] = (unsigned)__bfloat16_as_ushort(l0) | ((unsigned)__bfloat16_as_ushort(l1) << 16);
    }
    long ob = ((long)b * NPIX + p0 + lp) * DIMC + c0 + ch16;
    *(uint4*)(hi + ob)     = make_uint4(hw[0], hw[1], hw[2], hw[3]);
    *(uint4*)(hi + ob + 8) = make_uint4(hw[4], hw[5], hw[6], hw[7]);
    *(uint4*)(lo + ob)     = make_uint4(lw[0], lw[1], lw[2], lw[3]);
    *(uint4*)(lo + ob + 8) = make_uint4(lw[4], lw[5], lw[6], lw[7]);
}

// ---------------- HMMA bf16x3 GEMM, multi-stage cp.async ring ----------------
// (STAGES=2 instantiations reproduce the measured-best R12 schedule.)
template <int NCHT, int KD, int KC, int STAGES, int MW, int NW, int MF, int NF>
__global__ __launch_bounds__(256)
void gemm_mma(const __nv_bfloat16* __restrict__ Whi, const __nv_bfloat16* __restrict__ Wlo,
              const __nv_bfloat16* __restrict__ Xhi, const __nv_bfloat16* __restrict__ Xlo,
              const float* __restrict__ bias, float* __restrict__ C)
{
    constexpr int MT = MW * MF * 16;        // channel tile
    constexpr int CHUNKS = KD / KC;
    constexpr int ROWB = KC * 2 + 16;       // bytes per smem row (odd x16B)
    constexpr int QPR = KC / 8;             // uint4 per row
    constexpr int BUF = (2 * MT + 2 * 128) * ROWB;
    const int OF_AH = 0;
    const int OF_AL = MT * ROWB;
    const int OF_BH = 2 * MT * ROWB;
    const int OF_BL = 2 * MT * ROWB + 128 * ROWB;

    extern __shared__ char sm[];
    int tid = threadIdx.x;
    int wid = tid >> 5, lane = tid & 31;
    int pix0 = blockIdx.x * 128;
    int bb = blockIdx.y;
    int m0 = blockIdx.z * MT;

    uint32_t sbase = smem_u32(sm);

    int wm = wid % MW, wn = wid / MW;
    int mwo = wm * MF * 16;
    int nwo = wn * NF * 8;

    const __nv_bfloat16* Xh = Xhi + (long)bb * NPIX * KD;
    const __nv_bfloat16* Xl = Xlo + (long)bb * NPIX * KD;

    float acc[MF][NF][4];
    #pragma unroll
    for (int i = 0; i < MF; i++)
        #pragma unroll
        for (int j = 0; j < NF; j++)
            #pragma unroll
            for (int q = 0; q < 4; q++) acc[i][j][q] = 0.f;

    int a_row = lane & 15, a_col = (lane >> 4) << 3;
    int b_nrow = ((lane >> 4) << 3) + (lane & 7);
    int b_kcol = ((lane >> 3) & 1) << 3;

    auto prefetch = [&](int ck, int bsel) {
        uint32_t bpa = sbase + bsel * BUF;
        for (int i = tid; i < MT * QPR; i += 256) {
            int row = i / QPR, q = i % QPR;
            long src = (long)(m0 + row) * KD + ck * KC + q * 8;
            cpasync16(bpa + OF_AH + row * ROWB + q * 16, Whi + src);
            cpasync16(bpa + OF_AL + row * ROWB + q * 16, Wlo + src);
        }
        for (int i = tid; i < 128 * QPR; i += 256) {
            int row = i / QPR, q = i % QPR;
            long src = (long)(pix0 + row) * KD + ck * KC + q * 8;
            cpasync16(bpa + OF_BH + row * ROWB + q * 16, Xh + src);
            cpasync16(bpa + OF_BL + row * ROWB + q * 16, Xl + src);
        }
    };

    // prologue: stages 0..STAGES-2
    for (int s = 0; s < STAGES - 1; s++) {
        if (s < CHUNKS) prefetch(s, s);
        CP_COMMIT();
    }

    for (int ck = 0; ck < CHUNKS; ck++) {
        int pf = ck + STAGES - 1;
        if (pf < CHUNKS) prefetch(pf, pf % STAGES);
        CP_COMMIT();
        asm volatile("cp.async.wait_group %0;" :: "n"(STAGES - 1) : "memory");
        __syncthreads();

        uint32_t bpa = sbase + (ck % STAGES) * BUF;
        #pragma unroll
        for (int ks = 0; ks < KC / 16; ks++) {
            int ko = ks * 16;
            uint32_t ah[MF][4], al[MF][4], bh[NF][2], bl[NF][2];
            #pragma unroll
            for (int mi = 0; mi < MF; mi++) {
                uint32_t off = (mwo + mi * 16 + a_row) * ROWB + (ko + a_col) * 2;
                ldsm4(ah[mi], bpa + OF_AH + off);
                ldsm4(al[mi], bpa + OF_AL + off);
            }
            #pragma unroll
            for (int nj2 = 0; nj2 < NF / 2; nj2++) {
                uint32_t off = (nwo + nj2 * 16 + b_nrow) * ROWB + (ko + b_kcol) * 2;
                uint32_t t4[4];
                ldsm4(t4, bpa + OF_BH + off);
                bh[2 * nj2][0] = t4[0]; bh[2 * nj2][1] = t4[1];
                bh[2 * nj2 + 1][0] = t4[2]; bh[2 * nj2 + 1][1] = t4[3];
                ldsm4(t4, bpa + OF_BL + off);
                bl[2 * nj2][0] = t4[0]; bl[2 * nj2][1] = t4[1];
                bl[2 * nj2 + 1][0] = t4[2]; bl[2 * nj2 + 1][1] = t4[3];
            }
            #pragma unroll
            for (int mi = 0; mi < MF; mi++)
                #pragma unroll
                for (int nj = 0; nj < NF; nj++) {
                    mma16816(acc[mi][nj], ah[mi], bh[nj]);
                    mma16816(acc[mi][nj], ah[mi], bl[nj]);
                    mma16816(acc[mi][nj], al[mi], bh[nj]);
                }
        }
        __syncthreads();   // all warps done with this buffer before it is reused
    }

    // epilogue: bias + float2 stores into [b][ch][pix]
    int chl = lane >> 2, pxl = (lane & 3) << 1;
    #pragma unroll
    for (int mi = 0; mi < MF; mi++) {
        int ch = m0 + mwo + mi * 16 + chl;
        float bi0 = bias[ch], bi1 = bias[ch + 8];
        float* Crow0 = C + ((long)bb * NCHT + ch) * NPIX + pix0;
        float* Crow1 = Crow0 + 8 * NPIX;
        #pragma unroll
        for (int nj = 0; nj < NF; nj++) {
            int px = nwo + nj * 8 + pxl;
            *(float2*)(Crow0 + px) = make_float2(acc[mi][nj][0] + bi0, acc[mi][nj][1] + bi0);
            *(float2*)(Crow1 + px) = make_float2(acc[mi][nj][2] + bi1, acc[mi][nj][3] + bi1);
        }
    }
}

// ---------------- bf16 hi/lo split store of 8 channels ----------------
__device__ __forceinline__ void store8_split(__nv_bfloat16* hi, __nv_bfloat16* lo,
                                             long off, const float* v)
{
    unsigned hw[4], lw[4];
    #pragma unroll
    for (int j = 0; j < 4; j++) {
        __nv_bfloat16 h0 = __float2bfloat16(v[2 * j]);
        __nv_bfloat16 h1 = __float2bfloat16(v[2 * j + 1]);
        __nv_bfloat16 l0 = __float2bfloat16(v[2 * j] - __bfloat162float(h0));
        __nv_bfloat16 l1 = __float2bfloat16(v[2 * j + 1] - __bfloat162float(h1));
        hw[j] = (unsigned)__bfloat16_as_ushort(h0) | ((unsigned)__bfloat16_as_ushort(h1) << 16);
        lw[j] = (unsigned)__bfloat16_as_ushort(l0) | ((unsigned)__bfloat16_as_ushort(l1) << 16);
    }
    *(uint4*)(hi + off) = make_uint4(hw[0], hw[1], hw[2], hw[3]);
    *(uint4*)(lo + off) = make_uint4(lw[0], lw[1], lw[2], lw[3]);
}

// ---------------- slide attention, f32x2 packed: 4 px/thread ----------------
// 16x32 pixel tile, 128 threads. pack0=(r, c | c+16), pack1=(r+8, c | c+16).
__global__ __launch_bounds__(128)
void attn2_kernel(const float* __restrict__ qkv,
                  const float* __restrict__ dep_b0,
                  const float* __restrict__ dep_b1,
                  const float* __restrict__ W1,
                  const float* __restrict__ rpb,
                  __nv_bfloat16* __restrict__ at_hi,
                  __nv_bfloat16* __restrict__ at_lo)
{
    __shared__ float sk[8][18][34];
    __shared__ float sv[8][18][34];
    __shared__ u64 sw2[8][9][9];   // duplicated weights
    __shared__ u64 sbk2[72];       // dup(b0+b1+rpb)
    __shared__ u64 sbv2[72];       // dup(b0+b1)

    int bz = blockIdx.z;
    int b = bz >> 3, nh = bz & 7;
    int x0 = blockIdx.x * 32, y0 = blockIdx.y * 16;
    int tid = threadIdx.x;
    int tx = tid & 15, ty = tid >> 4;   // ty 0..7

    const float* base = qkv + ((long)b * QKVC + 24 * nh) * NPIX;

    for (int i = tid; i < 8 * 18 * 34; i += 128) {
        int c = i / 612;
        int r = (i / 34) % 18;
        int col = i % 34;
        int gy = y0 + r - 1, gx = x0 + col - 1;
        float kv = 0.f, vv = 0.f;
        if ((unsigned)gy < 64u && (unsigned)gx < 64u) {
            long off = (long)(8 + c) * NPIX + gy * WW + gx;
            kv = base[off];
            vv = base[off + 8 * NPIX];
        }
        sk[c][r][col] = kv;
        sv[c][r][col] = vv;
    }
    for (int i = tid; i < 648; i += 128) {
        float w = W1[i];
        ((u64*)sw2)[i] = pk2(w, w);
    }
    if (tid < 72) {
        float s = dep_b0[tid] + dep_b1[tid];
        float rk = s + rpb[nh * 9 + (tid % 9)];
        sbk2[tid] = pk2(rk, rk);
        sbv2[tid] = pk2(s, s);
    }
    __syncthreads();

    int pA = (y0 + ty) * WW + x0 + tx;
    int pB = pA + 16;
    int pC = pA + 8 * WW;
    int pD = pC + 16;

    u64 lg0[9], lg1[9];
    #pragma unroll
    for (int t = 0; t < 9; t++) { lg0[t] = 0ULL; lg1[t] = 0ULL; }

    // ---- logits ----
    #pragma unroll
    for (int c = 0; c < 8; c++) {
        const float* qb = base + (long)c * NPIX;
        u64 q20 = pk2(qb[pA] * SCALE, qb[pB] * SCALE);
        u64 q21 = pk2(qb[pC] * SCALE, qb[pD] * SCALE);
        u64 nb0[9], nb1[9];
        #pragma unroll
        for (int t = 0; t < 9; t++) {
            int dy = t / 3 - 1, dx = t % 3 - 1;
            nb0[t] = pk2(sk[c][ty + 1 + dy][tx + 1 + dx], sk[c][ty + 1 + dy][tx + 17 + dx]);
            nb1[t] = pk2(sk[c][ty + 9 + dy][tx + 1 + dx], sk[c][ty + 9 + dy][tx + 17 + dx]);
        }
        #pragma unroll
        for (int t = 0; t < 9; t++) {
            u64 bias = sbk2[c * 9 + t];
            u64 k0 = add2_(nb0[t], bias);
            u64 k1 = add2_(nb1[t], bias);
            #pragma unroll
            for (int s = 0; s < 9; s++) {
                u64 w = sw2[c][t][s];
                k0 = fma2(w, nb0[s], k0);
                k1 = fma2(w, nb1[s], k1);
            }
            lg0[t] = fma2(q20, k0, lg0[t]);
            lg1[t] = fma2(q21, k1, lg1[t]);
        }
    }

    // ---- softmax (4 independent pixels) ----
    float ea[9], eb[9], ec[9], ed[9];
    #pragma unroll
    for (int t = 0; t < 9; t++) {
        upk2(lg0[t], ea[t], eb[t]);
        upk2(lg1[t], ec[t], ed[t]);
    }
    float mA = ea[0], mB = eb[0], mC = ec[0], mD = ed[0];
    #pragma unroll
    for (int t = 1; t < 9; t++) {
        mA = fmaxf(mA, ea[t]); mB = fmaxf(mB, eb[t]);
        mC = fmaxf(mC, ec[t]); mD = fmaxf(mD, ed[t]);
    }
    float sA = 0.f, sB = 0.f, sC = 0.f, sD = 0.f;
    #pragma unroll
    for (int t = 0; t < 9; t++) {
        ea[t] = __expf(ea[t] - mA); sA += ea[t];
        eb[t] = __expf(eb[t] - mB); sB += eb[t];
        ec[t] = __expf(ec[t] - mC); sC += ec[t];
        ed[t] = __expf(ed[t] - mD); sD += ed[t];
    }
    float iA = 1.f / sA, iB = 1.f / sB, iC = 1.f / sC, iD = 1.f / sD;
    u64 at0[9], at1[9];
    #pragma unroll
    for (int t = 0; t < 9; t++) {
        at0[t] = pk2(ea[t], eb[t]);
        at1[t] = pk2(ec[t], ed[t]);
    }

    // ---- output (v path) ----
    float outA[8], outB[8], outC[8], outD[8];
    #pragma unroll
    for (int c = 0; c < 8; c++) {
        u64 nb0[9], nb1[9];
        #pragma unroll
        for (int t = 0; t < 9; t++) {
            int dy = t / 3 - 1, dx = t % 3 - 1;
            nb0[t] = pk2(sv[c][ty + 1 + dy][tx + 1 + dx], sv[c][ty + 1 + dy][tx + 17 + dx]);
            nb1[t] = pk2(sv[c][ty + 9 + dy][tx + 1 + dx], sv[c][ty + 9 + dy][tx + 17 + dx]);
        }
        u64 o0 = 0ULL, o1 = 0ULL;
        #pragma unroll
        for (int t = 0; t < 9; t++) {
            u64 bias = sbv2[c * 9 + t];
            u64 v0 = add2_(nb0[t], bias);
            u64 v1 = add2_(nb1[t], bias);
            #pragma unroll
            for (int s = 0; s < 9; s++) {
                u64 w = sw2[c][t][s];
                v0 = fma2(w, nb0[s], v0);
                v1 = fma2(w, nb1[s], v1);
            }
            o0 = fma2(at0[t], v0, o0);
            o1 = fma2(at1[t], v1, o1);
        }
        float fA, fB, fC, fD;
        upk2(o0, fA, fB);
        upk2(o1, fC, fD);
        outA[c] = fA * iA; outB[c] = fB * iB;
        outC[c] = fC * iC; outD[c] = fD * iD;
    }

    long rbase = ((long)b * NPIX) * CRCH + nh * 8;
    store8_split(at_hi, at_lo, rbase + (long)pA * CRCH, outA);
    store8_split(at_hi, at_lo, rbase + (long)pB * CRCH, outB);
    store8_split(at_hi, at_lo, rbase + (long)pC * CRCH, outC);
    store8_split(at_hi, at_lo, rbase + (long)pD * CRCH, outD);
}

// ---------------- launch ----------------
extern "C" void kernel_launch(void* const* d_in, const int* in_sizes, int n_in,
                              void* d_out, int out_size)
{
    const float* x      = (const float*)d_in[0];
    const float* qkv_w  = (const float*)d_in[5];
    const float* qkv_b  = (const float*)d_in[6];
    const float* dep_b0 = (const float*)d_in[7];
    const float* W1     = (const float*)d_in[8];
    const float* dep_b1 = (const float*)d_in[9];
    const float* rpb    = (const float*)d_in[10];
    const float* proj_w = (const float*)d_in[11];
    const float* proj_b = (const float*)d_in[12];
    float* out = (float*)d_out;

    float* qkvbuf; cudaGetSymbolAddress((void**)&qkvbuf, g_qkv);
    __nv_bfloat16 *xth, *xtl, *ath, *atl, *wh, *wl, *pwh, *pwl;
    cudaGetSymbolAddress((void**)&xth, g_xt_hi);
    cudaGetSymbolAddress((void**)&xtl, g_xt_lo);
    cudaGetSymbolAddress((void**)&ath, g_at_hi);
    cudaGetSymbolAddress((void**)&atl, g_at_lo);
    cudaGetSymbolAddress((void**)&wh, g_w_hi);
    cudaGetSymbolAddress((void**)&wl, g_w_lo);
    cudaGetSymbolAddress((void**)&pwh, g_pw_hi);
    cudaGetSymbolAddress((void**)&pwl, g_pw_lo);

    // R12 proven-best configs: GEMM1 KC=64 2-stage; GEMM3 KC=32 2-stage.
    auto k1 = gemm_mma<QKVC, DIMC, 64, 2, 4, 2, 3, 8>;
    auto k3 = gemm_mma<DIMC, CRCH, 32, 2, 2, 4, 4, 4>;
    const int SMEM1 = 2 * (2 * 192 + 2 * 128) * 144;   // 184320
    const int SMEM3 = 2 * (2 * 128 + 2 * 128) * 80;    // 81920
    cudaFuncSetAttribute(k1, cudaFuncAttributeMaxDynamicSharedMemorySize, SMEM1);
    cudaFuncSetAttribute(k3, cudaFuncAttributeMaxDynamicSharedMemorySize, SMEM3);

    // weight splits
    convert_split<<<(QKVC * DIMC + 255) / 256, 256>>>(qkv_w, wh, wl, QKVC * DIMC);
    convert_split<<<(DIMC * CRCH + 255) / 256, 256>>>(proj_w, pwh, pwl, DIMC * CRCH);

    // x transpose+split
    tconv_x<<<dim3(NPIX / 64, DIMC / 64, BATCH), 256>>>(x, xth, xtl);

    // GEMM1 -> qkv fp32 [b][192][4096]
    k1<<<dim3(NPIX / 128, BATCH, 1), 256, SMEM1>>>(wh, wl, xth, xtl, qkv_b, qkvbuf);

    // attention (f32x2 packed) -> at hi/lo [b][pix][64]
    attn2_kernel<<<dim3(2, 4, BATCH * NHEAD), 128>>>(
        qkvbuf, dep_b0, dep_b1, W1, rpb, ath, atl);

    // GEMM3 -> out [b][256][4096]
    k3<<<dim3(NPIX / 128, BATCH, 2), 256, SMEM3>>>(pwh, pwl, ath, atl, proj_b, out);
}

// round 17
// speedup vs baseline: 1.1403x; 1.0246x over previous
#include <cuda_runtime.h>
#include <cuda_bf16.h>
#include <cstdint>

#define BATCH 16
#define DIMC  256
#define NHEAD 8
#define CRCH  64
#define HH    64
#define WW    64
#define NPIX  (HH*WW)
#define QKVC  192
#define SCALE 0.17677669529663687f

typedef unsigned long long u64;

__device__ __forceinline__ uint32_t smem_u32(const void* p) {
    uint32_t a;
    asm("{ .reg .u64 t; cvta.to.shared.u64 t, %1; cvt.u32.u64 %0, t; }" : "=r"(a) : "l"(p));
    return a;
}
__device__ __forceinline__ void ldsm4(uint32_t* r, uint32_t addr) {
    asm volatile("ldmatrix.sync.aligned.m8n8.x4.shared.b16 {%0,%1,%2,%3}, [%4];"
        : "=r"(r[0]), "=r"(r[1]), "=r"(r[2]), "=r"(r[3]) : "r"(addr));
}
__device__ __forceinline__ void mma16816(float* d, const uint32_t* a, const uint32_t* b) {
    asm volatile("mma.sync.aligned.m16n8k16.row.col.f32.bf16.bf16.f32 "
        "{%0,%1,%2,%3}, {%4,%5,%6,%7}, {%8,%9}, {%0,%1,%2,%3};"
        : "+f"(d[0]), "+f"(d[1]), "+f"(d[2]), "+f"(d[3])
        : "r"(a[0]), "r"(a[1]), "r"(a[2]), "r"(a[3]), "r"(b[0]), "r"(b[1]));
}
__device__ __forceinline__ void cpasync16(uint32_t dst, const void* src) {
    asm volatile("cp.async.cg.shared.global [%0], [%1], 16;" :: "r"(dst), "l"(src));
}
#define CP_COMMIT() asm volatile("cp.async.commit_group;" ::: "memory")

// f32x2 packed helpers
__device__ __forceinline__ u64 pk2(float lo, float hi) {
    u64 r; asm("mov.b64 %0, {%1, %2};" : "=l"(r) : "f"(lo), "f"(hi)); return r;
}
__device__ __forceinline__ void upk2(u64 v, float& lo, float& hi) {
    asm("mov.b64 {%0, %1}, %2;" : "=f"(lo), "=f"(hi) : "l"(v));
}
__device__ __forceinline__ u64 fma2(u64 a, u64 b, u64 c) {
    u64 r; asm("fma.rn.f32x2 %0, %1, %2, %3;" : "=l"(r) : "l"(a), "l"(b), "l"(c)); return r;
}
__device__ __forceinline__ u64 add2_(u64 a, u64 b) {
    u64 r; asm("add.rn.f32x2 %0, %1, %2;" : "=l"(r) : "l"(a), "l"(b)); return r;
}

// ---------------- scratch ----------------
__device__ float g_qkv[(long)BATCH * QKVC * NPIX];            // (B,192,4096) fp32
__device__ __nv_bfloat16 g_xt_hi[(long)BATCH * NPIX * DIMC];  // (B,4096,256)
__device__ __nv_bfloat16 g_xt_lo[(long)BATCH * NPIX * DIMC];
__device__ __nv_bfloat16 g_at_hi[(long)BATCH * NPIX * CRCH];  // (B,4096,64)
__device__ __nv_bfloat16 g_at_lo[(long)BATCH * NPIX * CRCH];
__device__ __nv_bfloat16 g_w_hi[QKVC * DIMC];
__device__ __nv_bfloat16 g_w_lo[QKVC * DIMC];
__device__ __nv_bfloat16 g_pw_hi[DIMC * CRCH];
__device__ __nv_bfloat16 g_pw_lo[DIMC * CRCH];

// ---------------- weight split convert ----------------
__global__ void convert_split(const float* __restrict__ src,
                              __nv_bfloat16* __restrict__ hi,
                              __nv_bfloat16* __restrict__ lo, int n)
{
    int i = blockIdx.x * 256 + threadIdx.x;
    if (i < n) {
        float v = src[i];
        __nv_bfloat16 h = __float2bfloat16(v);
        hi[i] = h;
        lo[i] = __float2bfloat16(v - __bfloat162float(h));
    }
}

// ---------------- transpose + split convert of x ----------------
__global__ __launch_bounds__(256)
void tconv_x(const float* __restrict__ X,
             __nv_bfloat16* __restrict__ hi, __nv_bfloat16* __restrict__ lo)
{
    __shared__ float s[64][68];
    int b = blockIdx.z, c0 = blockIdx.y * 64, p0 = blockIdx.x * 64;
    const float* src = X + ((long)b * DIMC + c0) * NPIX + p0;
    int t = threadIdx.x;
    int lc = t >> 4, lp4 = (t & 15) * 4;
    #pragma unroll
    for (int i = 0; i < 4; i++) {
        float4 v = *(const float4*)(src + (long)(lc + i * 16) * NPIX + lp4);
        s[lc + i * 16][lp4 + 0] = v.x;
        s[lc + i * 16][lp4 + 1] = v.y;
        s[lc + i * 16][lp4 + 2] = v.z;
        s[lc + i * 16][lp4 + 3] = v.w;
    }
    __syncthreads();
    int lp = t >> 2, ch16 = (t & 3) * 16;
    unsigned hw[8], lw[8];
    #pragma unroll
    for (int j = 0; j < 8; j++) {
        float v0 = s[ch16 + 2 * j][lp];
        float v1 = s[ch16 + 2 * j + 1][lp];
        __nv_bfloat16 h0 = __float2bfloat16(v0);
        __nv_bfloat16 h1 = __float2bfloat16(v1);
        __nv_bfloat16 l0 = __float2bfloat16(v0 - __bfloat162float(h0));
        __nv_bfloat16 l1 = __float2bfloat16(v1 - __bfloat162float(h1));
        hw[j] = (unsigned)__bfloat16_as_ushort(h0) | ((unsigned)__bfloat16_as_ushort(h1) << 16);
        lw[j] = (unsigned)__bfloat16_as_ushort(l0) | ((unsigned)__bfloat16_as_ushort(l1) << 16);
    }
    long ob = ((long)b * NPIX + p0 + lp) * DIMC + c0 + ch16;
    *(uint4*)(hi + ob)     = make_uint4(hw[0], hw[1], hw[2], hw[3]);
    *(uint4*)(hi + ob + 8) = make_uint4(hw[4], hw[5], hw[6], hw[7]);
    *(uint4*)(lo + ob)     = make_uint4(lw[0], lw[1], lw[2], lw[3]);
    *(uint4*)(lo + ob + 8) = make_uint4(lw[4], lw[5], lw[6], lw[7]);
}

// ---------------- HMMA bf16x3 GEMM, cp.async ring, 2 CTAs/SM ----------------
template <int NCHT, int KD, int KC, int STAGES, int MW, int NW, int MF, int NF>
__global__ __launch_bounds__(256, 2)
void gemm_mma(const __nv_bfloat16* __restrict__ Whi, const __nv_bfloat16* __restrict__ Wlo,
              const __nv_bfloat16* __restrict__ Xhi, const __nv_bfloat16* __restrict__ Xlo,
              const float* __restrict__ bias, float* __restrict__ C)
{
    constexpr int MT = MW * MF * 16;        // channel tile
    constexpr int CHUNKS = KD / KC;
    constexpr int ROWB = KC * 2 + 16;       // bytes per smem row (odd x16B)
    constexpr int QPR = KC / 8;             // uint4 per row
    constexpr int BUF = (2 * MT + 2 * 128) * ROWB;
    const int OF_AH = 0;
    const int OF_AL = MT * ROWB;
    const int OF_BH = 2 * MT * ROWB;
    const int OF_BL = 2 * MT * ROWB + 128 * ROWB;

    extern __shared__ char sm[];
    int tid = threadIdx.x;
    int wid = tid >> 5, lane = tid & 31;
    int pix0 = blockIdx.x * 128;
    int bb = blockIdx.y;
    int m0 = blockIdx.z * MT;

    uint32_t sbase = smem_u32(sm);

    int wm = wid % MW, wn = wid / MW;
    int mwo = wm * MF * 16;
    int nwo = wn * NF * 8;

    const __nv_bfloat16* Xh = Xhi + (long)bb * NPIX * KD;
    const __nv_bfloat16* Xl = Xlo + (long)bb * NPIX * KD;

    float acc[MF][NF][4];
    #pragma unroll
    for (int i = 0; i < MF; i++)
        #pragma unroll
        for (int j = 0; j < NF; j++)
            #pragma unroll
            for (int q = 0; q < 4; q++) acc[i][j][q] = 0.f;

    int a_row = lane & 15, a_col = (lane >> 4) << 3;
    int b_nrow = ((lane >> 4) << 3) + (lane & 7);
    int b_kcol = ((lane >> 3) & 1) << 3;

    auto prefetch = [&](int ck, int bsel) {
        uint32_t bpa = sbase + bsel * BUF;
        for (int i = tid; i < MT * QPR; i += 256) {
            int row = i / QPR, q = i % QPR;
            long src = (long)(m0 + row) * KD + ck * KC + q * 8;
            cpasync16(bpa + OF_AH + row * ROWB + q * 16, Whi + src);
            cpasync16(bpa + OF_AL + row * ROWB + q * 16, Wlo + src);
        }
        for (int i = tid; i < 128 * QPR; i += 256) {
            int row = i / QPR, q = i % QPR;
            long src = (long)(pix0 + row) * KD + ck * KC + q * 8;
            cpasync16(bpa + OF_BH + row * ROWB + q * 16, Xh + src);
            cpasync16(bpa + OF_BL + row * ROWB + q * 16, Xl + src);
        }
    };

    // prologue: stages 0..STAGES-2
    for (int s = 0; s < STAGES - 1; s++) {
        if (s < CHUNKS) prefetch(s, s);
        CP_COMMIT();
    }

    for (int ck = 0; ck < CHUNKS; ck++) {
        int pf = ck + STAGES - 1;
        if (pf < CHUNKS) prefetch(pf, pf % STAGES);
        CP_COMMIT();
        asm volatile("cp.async.wait_group %0;" :: "n"(STAGES - 1) : "memory");
        __syncthreads();

        uint32_t bpa = sbase + (ck % STAGES) * BUF;
        #pragma unroll
        for (int ks = 0; ks < KC / 16; ks++) {
            int ko = ks * 16;
            uint32_t ah[MF][4], al[MF][4], bh[NF][2], bl[NF][2];
            #pragma unroll
            for (int mi = 0; mi < MF; mi++) {
                uint32_t off = (mwo + mi * 16 + a_row) * ROWB + (ko + a_col) * 2;
                ldsm4(ah[mi], bpa + OF_AH + off);
                ldsm4(al[mi], bpa + OF_AL + off);
            }
            #pragma unroll
            for (int nj2 = 0; nj2 < NF / 2; nj2++) {
                uint32_t off = (nwo + nj2 * 16 + b_nrow) * ROWB + (ko + b_kcol) * 2;
                uint32_t t4[4];
                ldsm4(t4, bpa + OF_BH + off);
                bh[2 * nj2][0] = t4[0]; bh[2 * nj2][1] = t4[1];
                bh[2 * nj2 + 1][0] = t4[2]; bh[2 * nj2 + 1][1] = t4[3];
                ldsm4(t4, bpa + OF_BL + off);
                bl[2 * nj2][0] = t4[0]; bl[2 * nj2][1] = t4[1];
                bl[2 * nj2 + 1][0] = t4[2]; bl[2 * nj2 + 1][1] = t4[3];
            }
            #pragma unroll
            for (int mi = 0; mi < MF; mi++)
                #pragma unroll
                for (int nj = 0; nj < NF; nj++) {
                    mma16816(acc[mi][nj], ah[mi], bh[nj]);
                    mma16816(acc[mi][nj], ah[mi], bl[nj]);
                    mma16816(acc[mi][nj], al[mi], bh[nj]);
                }
        }
        __syncthreads();   // all warps done with this buffer before it is reused
    }

    // epilogue: bias + float2 stores into [b][ch][pix]
    int chl = lane >> 2, pxl = (lane & 3) << 1;
    #pragma unroll
    for (int mi = 0; mi < MF; mi++) {
        int ch = m0 + mwo + mi * 16 + chl;
        float bi0 = bias[ch], bi1 = bias[ch + 8];
        float* Crow0 = C + ((long)bb * NCHT + ch) * NPIX + pix0;
        float* Crow1 = Crow0 + 8 * NPIX;
        #pragma unroll
        for (int nj = 0; nj < NF; nj++) {
            int px = nwo + nj * 8 + pxl;
            *(float2*)(Crow0 + px) = make_float2(acc[mi][nj][0] + bi0, acc[mi][nj][1] + bi0);
            *(float2*)(Crow1 + px) = make_float2(acc[mi][nj][2] + bi1, acc[mi][nj][3] + bi1);
        }
    }
}

// ---------------- bf16 hi/lo split store of 8 channels ----------------
__device__ __forceinline__ void store8_split(__nv_bfloat16* hi, __nv_bfloat16* lo,
                                             long off, const float* v)
{
    unsigned hw[4], lw[4];
    #pragma unroll
    for (int j = 0; j < 4; j++) {
        __nv_bfloat16 h0 = __float2bfloat16(v[2 * j]);
        __nv_bfloat16 h1 = __float2bfloat16(v[2 * j + 1]);
        __nv_bfloat16 l0 = __float2bfloat16(v[2 * j] - __bfloat162float(h0));
        __nv_bfloat16 l1 = __float2bfloat16(v[2 * j + 1] - __bfloat162float(h1));
        hw[j] = (unsigned)__bfloat16_as_ushort(h0) | ((unsigned)__bfloat16_as_ushort(h1) << 16);
        lw[j] = (unsigned)__bfloat16_as_ushort(l0) | ((unsigned)__bfloat16_as_ushort(l1) << 16);
    }
    *(uint4*)(hi + off) = make_uint4(hw[0], hw[1], hw[2], hw[3]);
    *(uint4*)(lo + off) = make_uint4(lw[0], lw[1], lw[2], lw[3]);
}

// ---------------- slide attention, f32x2 packed: 4 px/thread ----------------
__global__ __launch_bounds__(128)
void attn2_kernel(const float* __restrict__ qkv,
                  const float* __restrict__ dep_b0,
                  const float* __restrict__ dep_b1,
                  const float* __restrict__ W1,
                  const float* __restrict__ rpb,
                  __nv_bfloat16* __restrict__ at_hi,
                  __nv_bfloat16* __restrict__ at_lo)
{
    __shared__ float sk[8][18][34];
    __shared__ float sv[8][18][34];
    __shared__ u64 sw2[8][9][9];   // duplicated weights
    __shared__ u64 sbk2[72];       // dup(b0+b1+rpb)
    __shared__ u64 sbv2[72];       // dup(b0+b1)

    int bz = blockIdx.z;
    int b = bz >> 3, nh = bz & 7;
    int x0 = blockIdx.x * 32, y0 = blockIdx.y * 16;
    int tid = threadIdx.x;
    int tx = tid & 15, ty = tid >> 4;   // ty 0..7

    const float* base = qkv + ((long)b * QKVC + 24 * nh) * NPIX;

    for (int i = tid; i < 8 * 18 * 34; i += 128) {
        int c = i / 612;
        int r = (i / 34) % 18;
        int col = i % 34;
        int gy = y0 + r - 1, gx = x0 + col - 1;
        float kv = 0.f, vv = 0.f;
        if ((unsigned)gy < 64u && (unsigned)gx < 64u) {
            long off = (long)(8 + c) * NPIX + gy * WW + gx;
            kv = base[off];
            vv = base[off + 8 * NPIX];
        }
        sk[c][r][col] = kv;
        sv[c][r][col] = vv;
    }
    for (int i = tid; i < 648; i += 128) {
        float w = W1[i];
        ((u64*)sw2)[i] = pk2(w, w);
    }
    if (tid < 72) {
        float s = dep_b0[tid] + dep_b1[tid];
        float rk = s + rpb[nh * 9 + (tid % 9)];
        sbk2[tid] = pk2(rk, rk);
        sbv2[tid] = pk2(s, s);
    }
    __syncthreads();

    int pA = (y0 + ty) * WW + x0 + tx;
    int pB = pA + 16;
    int pC = pA + 8 * WW;
    int pD = pC + 16;

    u64 lg0[9], lg1[9];
    #pragma unroll
    for (int t = 0; t < 9; t++) { lg0[t] = 0ULL; lg1[t] = 0ULL; }

    // ---- logits ----
    #pragma unroll
    for (int c = 0; c < 8; c++) {
        const float* qb = base + (long)c * NPIX;
        u64 q20 = pk2(qb[pA] * SCALE, qb[pB] * SCALE);
        u64 q21 = pk2(qb[pC] * SCALE, qb[pD] * SCALE);
        u64 nb0[9], nb1[9];
        #pragma unroll
        for (int t = 0; t < 9; t++) {
            int dy = t / 3 - 1, dx = t % 3 - 1;
            nb0[t] = pk2(sk[c][ty + 1 + dy][tx + 1 + dx], sk[c][ty + 1 + dy][tx + 17 + dx]);
            nb1[t] = pk2(sk[c][ty + 9 + dy][tx + 1 + dx], sk[c][ty + 9 + dy][tx + 17 + dx]);
        }
        #pragma unroll
        for (int t = 0; t < 9; t++) {
            u64 bias = sbk2[c * 9 + t];
            u64 k0 = add2_(nb0[t], bias);
            u64 k1 = add2_(nb1[t], bias);
            #pragma unroll
            for (int s = 0; s < 9; s++) {
                u64 w = sw2[c][t][s];
                k0 = fma2(w, nb0[s], k0);
                k1 = fma2(w, nb1[s], k1);
            }
            lg0[t] = fma2(q20, k0, lg0[t]);
            lg1[t] = fma2(q21, k1, lg1[t]);
        }
    }

    // ---- softmax (4 independent pixels) ----
    float ea[9], eb[9], ec[9], ed[9];
    #pragma unroll
    for (int t = 0; t < 9; t++) {
        upk2(lg0[t], ea[t], eb[t]);
        upk2(lg1[t], ec[t], ed[t]);
    }
    float mA = ea[0], mB = eb[0], mC = ec[0], mD = ed[0];
    #pragma unroll
    for (int t = 1; t < 9; t++) {
        mA = fmaxf(mA, ea[t]); mB = fmaxf(mB, eb[t]);
        mC = fmaxf(mC, ec[t]); mD = fmaxf(mD, ed[t]);
    }
    float sA = 0.f, sB = 0.f, sC = 0.f, sD = 0.f;
    #pragma unroll
    for (int t = 0; t < 9; t++) {
        ea[t] = __expf(ea[t] - mA); sA += ea[t];
        eb[t] = __expf(eb[t] - mB); sB += eb[t];
        ec[t] = __expf(ec[t] - mC); sC += ec[t];
        ed[t] = __expf(ed[t] - mD); sD += ed[t];
    }
    float iA = 1.f / sA, iB = 1.f / sB, iC = 1.f / sC, iD = 1.f / sD;
    u64 at0[9], at1[9];
    #pragma unroll
    for (int t = 0; t < 9; t++) {
        at0[t] = pk2(ea[t], eb[t]);
        at1[t] = pk2(ec[t], ed[t]);
    }

    // ---- output (v path) ----
    float outA[8], outB[8], outC[8], outD[8];
    #pragma unroll
    for (int c = 0; c < 8; c++) {
        u64 nb0[9], nb1[9];
        #pragma unroll
        for (int t = 0; t < 9; t++) {
            int dy = t / 3 - 1, dx = t % 3 - 1;
            nb0[t] = pk2(sv[c][ty + 1 + dy][tx + 1 + dx], sv[c][ty + 1 + dy][tx + 17 + dx]);
            nb1[t] = pk2(sv[c][ty + 9 + dy][tx + 1 + dx], sv[c][ty + 9 + dy][tx + 17 + dx]);
        }
        u64 o0 = 0ULL, o1 = 0ULL;
        #pragma unroll
        for (int t = 0; t < 9; t++) {
            u64 bias = sbv2[c * 9 + t];
            u64 v0 = add2_(nb0[t], bias);
            u64 v1 = add2_(nb1[t], bias);
            #pragma unroll
            for (int s = 0; s < 9; s++) {
                u64 w = sw2[c][t][s];
                v0 = fma2(w, nb0[s], v0);
                v1 = fma2(w, nb1[s], v1);
            }
            o0 = fma2(at0[t], v0, o0);
            o1 = fma2(at1[t], v1, o1);
        }
        float fA, fB, fC, fD;
        upk2(o0, fA, fB);
        upk2(o1, fC, fD);
        outA[c] = fA * iA; outB[c] = fB * iB;
        outC[c] = fC * iC; outD[c] = fD * iD;
    }

    long rbase = ((long)b * NPIX) * CRCH + nh * 8;
    store8_split(at_hi, at_lo, rbase + (long)pA * CRCH, outA);
    store8_split(at_hi, at_lo, rbase + (long)pB * CRCH, outB);
    store8_split(at_hi, at_lo, rbase + (long)pC * CRCH, outC);
    store8_split(at_hi, at_lo, rbase + (long)pD * CRCH, outD);
}

// ---------------- launch ----------------
extern "C" void kernel_launch(void* const* d_in, const int* in_sizes, int n_in,
                              void* d_out, int out_size)
{
    const float* x      = (const float*)d_in[0];
    const float* qkv_w  = (const float*)d_in[5];
    const float* qkv_b  = (const float*)d_in[6];
    const float* dep_b0 = (const float*)d_in[7];
    const float* W1     = (const float*)d_in[8];
    const float* dep_b1 = (const float*)d_in[9];
    const float* rpb    = (const float*)d_in[10];
    const float* proj_w = (const float*)d_in[11];
    const float* proj_b = (const float*)d_in[12];
    float* out = (float*)d_out;

    float* qkvbuf; cudaGetSymbolAddress((void**)&qkvbuf, g_qkv);
    __nv_bfloat16 *xth, *xtl, *ath, *atl, *wh, *wl, *pwh, *pwl;
    cudaGetSymbolAddress((void**)&xth, g_xt_hi);
    cudaGetSymbolAddress((void**)&xtl, g_xt_lo);
    cudaGetSymbolAddress((void**)&ath, g_at_hi);
    cudaGetSymbolAddress((void**)&atl, g_at_lo);
    cudaGetSymbolAddress((void**)&wh, g_w_hi);
    cudaGetSymbolAddress((void**)&wl, g_w_lo);
    cudaGetSymbolAddress((void**)&pwh, g_pw_hi);
    cudaGetSymbolAddress((void**)&pwl, g_pw_lo);

    // 2-CTA/SM configs: GEMM1 MT=64 (z=3), KC=64 2-stage; GEMM3 MT=64 (z=4), KC=32 2-stage.
    auto k1 = gemm_mma<QKVC, DIMC, 64, 2, 4, 2, 1, 8>;
    auto k3 = gemm_mma<DIMC, CRCH, 32, 2, 2, 4, 2, 4>;
    const int SMEM1 = 2 * (2 * 64 + 2 * 128) * 144;   // 110592
    const int SMEM3 = 2 * (2 * 64 + 2 * 128) * 80;    // 61440
    cudaFuncSetAttribute(k1, cudaFuncAttributeMaxDynamicSharedMemorySize, SMEM1);
    cudaFuncSetAttribute(k3, cudaFuncAttributeMaxDynamicSharedMemorySize, SMEM3);

    // weight splits
    convert_split<<<(QKVC * DIMC + 255) / 256, 256>>>(qkv_w, wh, wl, QKVC * DIMC);
    convert_split<<<(DIMC * CRCH + 255) / 256, 256>>>(proj_w, pwh, pwl, DIMC * CRCH);

    // x transpose+split
    tconv_x<<<dim3(NPIX / 64, DIMC / 64, BATCH), 256>>>(x, xth, xtl);

    // GEMM1 -> qkv fp32 [b][192][4096]
    k1<<<dim3(NPIX / 128, BATCH, 3), 256, SMEM1>>>(wh, wl, xth, xtl, qkv_b, qkvbuf);

    // attention (f32x2 packed) -> at hi/lo [b][pix][64]
    attn2_kernel<<<dim3(2, 4, BATCH * NHEAD), 128>>>(
        qkvbuf, dep_b0, dep_b1, W1, rpb, ath, atl);

    // GEMM3 -> out [b][256][4096]
    k3<<<dim3(NPIX / 128, BATCH, 4), 256, SMEM3>>>(pwh, pwl, ath, atl, proj_b, out);
}